// round 14
// baseline (speedup 1.0000x reference)
#include <cuda_runtime.h>
#include <cuda_bf16.h>
#include <cstdint>
#include <math.h>

#define WD 16384
constexpr int Bsz   = 8;
constexpr int C     = 256;   // CIN == HID
constexpr int HEADS = 8;
constexpr int KW    = 31;
constexpr int PAD   = 15;

// ---- scratch (device globals: allocation-free) ----
__device__ float g_qWk[C * HEADS];
__device__ float g_qb[HEADS];
__device__ float g_cexp[(size_t)Bsz * HEADS * WD];       // 4 MB
__device__ float g_srec[(size_t)Bsz * HEADS * WD];       // 4 MB (1/sum_c)
__device__ float g_vc [(size_t)Bsz * C * WD];            // 128 MB
// pre-split bf16 operand planes
__device__ __nv_bfloat16 g_xhi[(size_t)Bsz * C * WD];    // 64 MB
__device__ __nv_bfloat16 g_xlo[(size_t)Bsz * C * WD];    // 64 MB
__device__ __nv_bfloat16 g_uhi[(size_t)Bsz * C * WD];    // 64 MB
__device__ __nv_bfloat16 g_ulo[(size_t)Bsz * C * WD];    // 64 MB
__device__ __nv_bfloat16 g_wvhi[C * C], g_wvlo[C * C];
__device__ __nv_bfloat16 g_wohi[C * C], g_wolo[C * C];

// ===========================================================================
// portable PTX helpers (sm_80-level only; no 'a' features)
// ===========================================================================
__device__ __forceinline__ uint32_t smem_u32(const void* p) {
    uint32_t a;
    asm("{ .reg .u64 t; cvta.to.shared.u64 t, %1; cvt.u32.u64 %0, t; }" : "=r"(a) : "l"(p));
    return a;
}
__device__ __forceinline__ void ldm_x4(uint32_t* r, uint32_t addr) {
    asm volatile("ldmatrix.sync.aligned.m8n8.x4.shared.b16 {%0,%1,%2,%3}, [%4];"
        : "=r"(r[0]), "=r"(r[1]), "=r"(r[2]), "=r"(r[3]) : "r"(addr));
}
__device__ __forceinline__ void ldm_x4_t(uint32_t* r, uint32_t addr) {
    asm volatile("ldmatrix.sync.aligned.m8n8.x4.trans.shared.b16 {%0,%1,%2,%3}, [%4];"
        : "=r"(r[0]), "=r"(r[1]), "=r"(r[2]), "=r"(r[3]) : "r"(addr));
}
__device__ __forceinline__ void mma_bf16(float* d, const uint32_t* a, const uint32_t* b) {
    asm volatile("mma.sync.aligned.m16n8k16.row.col.f32.bf16.bf16.f32 "
        "{%0,%1,%2,%3}, {%4,%5,%6,%7}, {%8,%9}, {%0,%1,%2,%3};"
        : "+f"(d[0]), "+f"(d[1]), "+f"(d[2]), "+f"(d[3])
        : "r"(a[0]), "r"(a[1]), "r"(a[2]), "r"(a[3]), "r"(b[0]), "r"(b[1]));
}
#define CP16(dst, src) asm volatile("cp.async.cg.shared.global [%0], [%1], 16;" :: "r"(dst), "l"(src) : "memory")
#define CP_COMMIT()    asm volatile("cp.async.commit_group;" ::: "memory")
#define CP_WAIT(n)     asm volatile("cp.async.wait_group %0;" :: "n"(n) : "memory")

__device__ __forceinline__ void split2(float v, __nv_bfloat16& h, __nv_bfloat16& l) {
    h = __float2bfloat16(v);
    l = __float2bfloat16(v - __bfloat162float(h));
}

// ===========================================================================
// K1: query prep
// ===========================================================================
__global__ void k_prep(const float* __restrict__ query,
                       const float* __restrict__ Wk,
                       const float* __restrict__ Wk_bias)
{
    __shared__ float qn[C];
    int t = threadIdx.x;
    float qv = query[t];
    float ss = qv * qv;
    #pragma unroll
    for (int o = 16; o > 0; o >>= 1) ss += __shfl_xor_sync(0xffffffffu, ss, o);
    float nrm = sqrtf(ss) + 1e-6f;
    float qnv = (qv / nrm) * 0.17677669529663687f;
    qn[t] = qnv;
    float bb = qnv * Wk_bias[t];
    #pragma unroll
    for (int o = 16; o > 0; o >>= 1) bb += __shfl_xor_sync(0xffffffffu, bb, o);
    if ((t & 31) == 0) g_qb[t >> 5] = bb;
    __syncthreads();
    #pragma unroll
    for (int h = 0; h < HEADS; h++) {
        float acc = 0.f;
        #pragma unroll
        for (int e = 0; e < 32; e++)
            acc += qn[h * 32 + e] * Wk[t * C + h * 32 + e];
        g_qWk[t * HEADS + h] = acc;
    }
}

// ===========================================================================
// K1b: weight split (both matrices)
// ===========================================================================
__global__ void k_wcvt(const float* __restrict__ Wv, const float* __restrict__ Wo)
{
    int i = blockIdx.x * 256 + threadIdx.x;
    split2(Wv[i], g_wvhi[i], g_wvlo[i]);
    split2(Wo[i], g_wohi[i], g_wolo[i]);
}

// ===========================================================================
// K2: cost_exp + x split (fused: single pass over x)
// ===========================================================================
__global__ __launch_bounds__(256)
void k_cost(const float* __restrict__ x)
{
    __shared__ float sQ[C * HEADS];
    __shared__ float sqb[HEADS];
    int t = threadIdx.x;
    for (int i = t; i < C * HEADS; i += 256) sQ[i] = g_qWk[i];
    if (t < HEADS) sqb[t] = g_qb[t];
    __syncthreads();

    int b = blockIdx.y;
    int w = blockIdx.x * 256 + t;
    size_t bC = (size_t)b * C;
    const float* xp = x + bC * WD + w;

    float acc[HEADS];
    #pragma unroll
    for (int h = 0; h < HEADS; h++) acc[h] = sqb[h];
    for (int d = 0; d < C; d++) {
        float xv = xp[(size_t)d * WD];
        __nv_bfloat16 hh, ll;
        split2(xv, hh, ll);
        size_t off = (bC + d) * WD + w;
        g_xhi[off] = hh;
        g_xlo[off] = ll;
        #pragma unroll
        for (int h = 0; h < HEADS; h++) acc[h] += xv * sQ[d * HEADS + h];
    }
    #pragma unroll
    for (int h = 0; h < HEADS; h++)
        g_cexp[((size_t)(b * HEADS + h)) * WD + w] = expf(acc[h]);
}

// ===========================================================================
// split-bf16 mma.sync GEMM, CTA tile 256(o) x 128(w) — B read exactly once.
// 8 warps: 4 along M x 2 along N; warp tile 64x64. K chunks of 32,
// 3-stage cp.async pipeline (48KB/stage), ONE __syncthreads per chunk:
//   wait(1) -> sync -> issue chunk c+2 -> compute chunk c
// 3 passes: AhiBhi + AloBhi + AhiBlo.
// MODE 0: B = xhi/xlo, Out = g_vc, epilogue (acc+bias)*cexp
// MODE 1: B = uhi/ulo, Out = param, epilogue acc+bias
// ===========================================================================
constexpr int KC    = 32;
constexpr int OF_A  = 0;        // 256 rows x 128B (hi chunks 0-3 | lo 4-7)  32KB
constexpr int OF_BH = 32768;    // 32 rows x 256B                            8KB
constexpr int OF_BL = 40960;    //                                           8KB
constexpr int STAGE = 49152;
constexpr int GSMEM = 3 * STAGE;   // 147456

template <int MODE>
__global__ __launch_bounds__(256, 1)
void k_mma_gemm(const float* __restrict__ bias, float* __restrict__ OutP)
{
    extern __shared__ char smem[];
    uint32_t sb = smem_u32(smem);
    int t   = threadIdx.x;
    int wid = t >> 5;
    int lid = t & 31;
    int b   = blockIdx.z;
    int w0  = blockIdx.x * 128;
    size_t bC = (size_t)b * C;

    const __nv_bfloat16* whi = (MODE == 0) ? g_wvhi : g_wohi;
    const __nv_bfloat16* wlo = (MODE == 0) ? g_wvlo : g_wolo;
    const __nv_bfloat16* bhi = (MODE == 0) ? g_xhi : g_uhi;
    const __nv_bfloat16* blo = (MODE == 0) ? g_xlo : g_ulo;
    float* Out = (MODE == 0) ? g_vc : OutP;

    int wm = (wid >> 1) * 64;     // warp M offset (0,64,128,192)
    int wn = (wid & 1) * 64;      // warp N offset (0,64)

    float acc[4][8][4];
    #pragma unroll
    for (int f = 0; f < 4; f++)
        #pragma unroll
        for (int nf = 0; nf < 8; nf++)
            #pragma unroll
            for (int i = 0; i < 4; i++) acc[f][nf][i] = 0.f;

    auto load_chunk = [&](int k0, int stg) {
        uint32_t base = sb + stg * STAGE;
        // A: 256 rows, 8x16B chunks per row (hi 0-3 | lo 4-7), swizzled
        #pragma unroll
        for (int j = 0; j < 8; j++) {
            int l = t + 256 * j;          // 0..2047
            int row = l >> 3;
            int c = l & 7;
            const __nv_bfloat16* src = ((c < 4) ? whi : wlo)
                                       + (size_t)row * C + k0 + (c & 3) * 8;
            CP16(base + OF_A + row * 128 + ((c ^ (row & 7)) << 4), src);
        }
        // B: [k][n] rows of 256B, hi and lo planes
        #pragma unroll
        for (int j = 0; j < 4; j++) {
            int l = t + 256 * j;          // 0..1023
            int plane = l >> 9;           // 0 = hi, 1 = lo
            int r = (l >> 4) & 31;
            int cc = l & 15;
            const __nv_bfloat16* src = (plane ? blo : bhi)
                                       + (bC + k0 + r) * WD + w0 + cc * 8;
            uint32_t off = (plane ? OF_BL : OF_BH) + r * 256 + ((cc ^ (r & 7)) << 4);
            CP16(base + off, src);
        }
    };

    load_chunk(0, 0); CP_COMMIT();
    load_chunk(KC, 1); CP_COMMIT();

    for (int c = 0; c < 8; c++) {
        if (c < 7) { CP_WAIT(1); } else { CP_WAIT(0); }
        __syncthreads();
        if (c + 2 < 8) { load_chunk((c + 2) * KC, (c + 2) % 3); CP_COMMIT(); }

        uint32_t Ab = sb + (c % 3) * STAGE + OF_A;
        uint32_t BH = sb + (c % 3) * STAGE + OF_BH;
        uint32_t BL = sb + (c % 3) * STAGE + OF_BL;

        #pragma unroll
        for (int ks = 0; ks < 2; ks++) {
            // A frags: 4 m16 frags hi + 4 lo
            uint32_t ah[4][4], al[4][4];
            #pragma unroll
            for (int f = 0; f < 4; f++) {
                int r  = wm + f * 16 + (lid & 15);
                int kc = 2 * ks + (lid >> 4);
                ldm_x4(ah[f], Ab + r * 128 + ((kc ^ (r & 7)) << 4));
                ldm_x4(al[f], Ab + r * 128 + (((kc + 4) ^ (r & 7)) << 4));
            }
            // B hi frags (trans ldmatrix on [k][n])
            int m    = lid >> 3;
            int krow = ks * 16 + (m & 1) * 8 + (lid & 7);
            int ccb  = (wn >> 3) + (m >> 1);
            uint32_t bh[16];
            #pragma unroll
            for (int p = 0; p < 4; p++) {
                int cc = ccb + 2 * p;
                ldm_x4_t(bh + 4 * p, BH + krow * 256 + ((cc ^ (krow & 7)) << 4));
            }
            #pragma unroll
            for (int f = 0; f < 4; f++)
                #pragma unroll
                for (int nf = 0; nf < 8; nf++) {
                    mma_bf16(acc[f][nf], ah[f], bh + 2 * nf);
                    mma_bf16(acc[f][nf], al[f], bh + 2 * nf);
                }
            // B lo frags
            uint32_t bl[16];
            #pragma unroll
            for (int p = 0; p < 4; p++) {
                int cc = ccb + 2 * p;
                ldm_x4_t(bl + 4 * p, BL + krow * 256 + ((cc ^ (krow & 7)) << 4));
            }
            #pragma unroll
            for (int f = 0; f < 4; f++)
                #pragma unroll
                for (int nf = 0; nf < 8; nf++)
                    mma_bf16(acc[f][nf], ah[f], bl + 2 * nf);
        }
        __syncthreads();
    }

    // ---- epilogue: fragment-direct float2 stores ----
    #pragma unroll
    for (int f = 0; f < 4; f++) {
        int rbase = wm + f * 16;
        int h = rbase >> 5;
        const float* ce = g_cexp + ((size_t)(b * HEADS + h)) * WD + w0;
        #pragma unroll
        for (int half = 0; half < 2; half++) {
            int o = rbase + (lid >> 2) + half * 8;
            float bvv = bias[o];
            float* op = Out + (bC + o) * WD + w0;
            #pragma unroll
            for (int nf = 0; nf < 8; nf++) {
                int wc = wn + nf * 8 + (lid & 3) * 2;
                float vx = acc[f][nf][half * 2 + 0];
                float vy = acc[f][nf][half * 2 + 1];
                float2 r;
                if (MODE == 0) {
                    float2 cc = *(const float2*)(ce + wc);
                    r.x = (vx + bvv) * cc.x;
                    r.y = (vy + bvv) * cc.y;
                } else {
                    r.x = vx + bvv;
                    r.y = vy + bvv;
                }
                *(float2*)(op + wc) = r;
            }
        }
    }
}

// ===========================================================================
// K4a: denominator reciprocal
// ===========================================================================
constexpr int CT = 1024;

__global__ __launch_bounds__(256)
void k_sumc(const float* __restrict__ rpe)
{
    __shared__ float sce[CT + 2 * PAD];
    __shared__ float srk[KW];
    int t  = threadIdx.x;
    int h  = blockIdx.y;
    int b  = blockIdx.z;
    int w0 = blockIdx.x * CT;

    if (t < KW) srk[t] = expf(rpe[h * KW + t]);
    const float* ce = g_cexp + ((size_t)(b * HEADS + h)) * WD;
    for (int i = t; i < CT + 2 * PAD; i += 256) {
        int g = w0 - PAD + i;
        sce[i] = (g >= 0 && g < WD) ? ce[g] : 0.f;
    }
    __syncthreads();

    float rk[KW];
    #pragma unroll
    for (int k = 0; k < KW; k++) rk[k] = srk[k];

    int base = t * 4;
    float win[34];
    #pragma unroll
    for (int j = 0; j < 34; j++) win[j] = sce[base + j];

    float s0 = 0.f, s1 = 0.f, s2 = 0.f, s3 = 0.f;
    #pragma unroll
    for (int k = 0; k < KW; k++) {
        float r = rk[k];
        s0 += r * win[k];     s1 += r * win[k + 1];
        s2 += r * win[k + 2]; s3 += r * win[k + 3];
    }
    float4 o;
    o.x = 1.f / s0; o.y = 1.f / s1; o.z = 1.f / s2; o.w = 1.f / s3;
    *(float4*)&g_srec[((size_t)(b * HEADS + h)) * WD + w0 + base] = o;
}

// ===========================================================================
// K4b: numerator conv + scale -> u split directly to bf16 hi/lo
// ===========================================================================
__global__ __launch_bounds__(256)
void k_conv(const float* __restrict__ rpe)
{
    __shared__ float svc[CT + 2 * PAD];
    __shared__ float srk[KW];
    int t  = threadIdx.x;
    int c  = blockIdx.y;
    int b  = blockIdx.z;
    int w0 = blockIdx.x * CT;
    int h  = c >> 5;

    if (t < KW) srk[t] = expf(rpe[h * KW + t]);
    const float* vcrow = g_vc + ((size_t)(b * C + c)) * WD;
    for (int i = t; i < CT + 2 * PAD; i += 256) {
        int g = w0 - PAD + i;
        svc[i] = (g >= 0 && g < WD) ? vcrow[g] : 0.f;
    }
    __syncthreads();

    float rk[KW];
    #pragma unroll
    for (int k = 0; k < KW; k++) rk[k] = srk[k];

    int base = t * 4;
    float win[34];
    #pragma unroll
    for (int j = 0; j < 34; j++) win[j] = svc[base + j];

    float s0 = 0.f, s1 = 0.f, s2 = 0.f, s3 = 0.f;
    #pragma unroll
    for (int k = 0; k < KW; k++) {
        float r = rk[k];
        s0 += r * win[k];     s1 += r * win[k + 1];
        s2 += r * win[k + 2]; s3 += r * win[k + 3];
    }
    float4 rec = *(const float4*)&g_srec[((size_t)(b * HEADS + h)) * WD + w0 + base];
    float u[4] = { s0 * rec.x, s1 * rec.y, s2 * rec.z, s3 * rec.w };

    size_t off = ((size_t)(b * C + c)) * WD + w0 + base;
    __nv_bfloat16 hh[4], ll[4];
    #pragma unroll
    for (int i = 0; i < 4; i++) split2(u[i], hh[i], ll[i]);
    *(uint2*)&g_uhi[off] = *(uint2*)hh;
    *(uint2*)&g_ulo[off] = *(uint2*)ll;
}

// ===========================================================================
extern "C" void kernel_launch(void* const* d_in, const int* in_sizes, int n_in,
                              void* d_out, int out_size)
{
    (void)in_sizes; (void)n_in; (void)out_size;
    const float* x     = (const float*)d_in[0];
    const float* query = (const float*)d_in[1];
    const float* Wk    = (const float*)d_in[2];
    const float* Wkb   = (const float*)d_in[3];
    const float* rpe   = (const float*)d_in[4];
    const float* Wv    = (const float*)d_in[5];
    const float* bv    = (const float*)d_in[6];
    const float* Wo    = (const float*)d_in[7];
    const float* bo    = (const float*)d_in[8];
    float* out = (float*)d_out;

    cudaFuncSetAttribute(k_mma_gemm<0>, cudaFuncAttributeMaxDynamicSharedMemorySize, GSMEM);
    cudaFuncSetAttribute(k_mma_gemm<1>, cudaFuncAttributeMaxDynamicSharedMemorySize, GSMEM);

    k_prep<<<1, 256>>>(query, Wk, Wkb);
    k_wcvt<<<C * C / 256, 256>>>(Wv, Wo);
    k_cost<<<dim3(WD / 256, Bsz), 256>>>(x);
    k_sumc<<<dim3(WD / CT, HEADS, Bsz), 256>>>(rpe);
    k_mma_gemm<0><<<dim3(WD / 128, 1, Bsz), 256, GSMEM>>>(bv, nullptr);
    k_conv<<<dim3(WD / CT, C, Bsz), 256>>>(rpe);
    k_mma_gemm<1><<<dim3(WD / 128, 1, Bsz), 256, GSMEM>>>(bo, out);
}

// round 17
// speedup vs baseline: 1.0667x; 1.0667x over previous
#include <cuda_runtime.h>
#include <cuda_bf16.h>
#include <cstdint>
#include <math.h>

#define WD 16384
constexpr int Bsz   = 8;
constexpr int C     = 256;   // CIN == HID
constexpr int HEADS = 8;
constexpr int KW    = 31;
constexpr int PAD   = 15;

// ---- scratch (device globals: allocation-free) ----
__device__ float g_qWk[C * HEADS];
__device__ float g_qb[HEADS];
__device__ float g_cexp[(size_t)Bsz * HEADS * WD];       // 4 MB
__device__ float g_srec[(size_t)Bsz * HEADS * WD];       // 4 MB (1/sum_c)
__device__ float g_vc [(size_t)Bsz * C * WD];            // 128 MB
// pre-split bf16 operand planes
__device__ __nv_bfloat16 g_xhi[(size_t)Bsz * C * WD];    // 64 MB
__device__ __nv_bfloat16 g_xlo[(size_t)Bsz * C * WD];    // 64 MB
__device__ __nv_bfloat16 g_uhi[(size_t)Bsz * C * WD];    // 64 MB
__device__ __nv_bfloat16 g_ulo[(size_t)Bsz * C * WD];    // 64 MB
__device__ __nv_bfloat16 g_wvhi[C * C], g_wvlo[C * C];
__device__ __nv_bfloat16 g_wohi[C * C], g_wolo[C * C];

// ===========================================================================
// portable PTX helpers (sm_80-level only; no 'a' features)
// ===========================================================================
__device__ __forceinline__ uint32_t smem_u32(const void* p) {
    uint32_t a;
    asm("{ .reg .u64 t; cvta.to.shared.u64 t, %1; cvt.u32.u64 %0, t; }" : "=r"(a) : "l"(p));
    return a;
}
__device__ __forceinline__ void ldm_x4(uint32_t* r, uint32_t addr) {
    asm volatile("ldmatrix.sync.aligned.m8n8.x4.shared.b16 {%0,%1,%2,%3}, [%4];"
        : "=r"(r[0]), "=r"(r[1]), "=r"(r[2]), "=r"(r[3]) : "r"(addr));
}
__device__ __forceinline__ void ldm_x4_t(uint32_t* r, uint32_t addr) {
    asm volatile("ldmatrix.sync.aligned.m8n8.x4.trans.shared.b16 {%0,%1,%2,%3}, [%4];"
        : "=r"(r[0]), "=r"(r[1]), "=r"(r[2]), "=r"(r[3]) : "r"(addr));
}
__device__ __forceinline__ void mma_bf16(float* d, const uint32_t* a, const uint32_t* b) {
    asm volatile("mma.sync.aligned.m16n8k16.row.col.f32.bf16.bf16.f32 "
        "{%0,%1,%2,%3}, {%4,%5,%6,%7}, {%8,%9}, {%0,%1,%2,%3};"
        : "+f"(d[0]), "+f"(d[1]), "+f"(d[2]), "+f"(d[3])
        : "r"(a[0]), "r"(a[1]), "r"(a[2]), "r"(a[3]), "r"(b[0]), "r"(b[1]));
}
#define CP16(dst, src) asm volatile("cp.async.cg.shared.global [%0], [%1], 16;" :: "r"(dst), "l"(src) : "memory")
#define CP_COMMIT()    asm volatile("cp.async.commit_group;" ::: "memory")
#define CP_WAIT(n)     asm volatile("cp.async.wait_group %0;" :: "n"(n) : "memory")

__device__ __forceinline__ void split2(float v, __nv_bfloat16& h, __nv_bfloat16& l) {
    h = __float2bfloat16(v);
    l = __float2bfloat16(v - __bfloat162float(h));
}

// ===========================================================================
// K1: query prep
// ===========================================================================
__global__ void k_prep(const float* __restrict__ query,
                       const float* __restrict__ Wk,
                       const float* __restrict__ Wk_bias)
{
    __shared__ float qn[C];
    int t = threadIdx.x;
    float qv = query[t];
    float ss = qv * qv;
    #pragma unroll
    for (int o = 16; o > 0; o >>= 1) ss += __shfl_xor_sync(0xffffffffu, ss, o);
    float nrm = sqrtf(ss) + 1e-6f;
    float qnv = (qv / nrm) * 0.17677669529663687f;
    qn[t] = qnv;
    float bb = qnv * Wk_bias[t];
    #pragma unroll
    for (int o = 16; o > 0; o >>= 1) bb += __shfl_xor_sync(0xffffffffu, bb, o);
    if ((t & 31) == 0) g_qb[t >> 5] = bb;
    __syncthreads();
    #pragma unroll
    for (int h = 0; h < HEADS; h++) {
        float acc = 0.f;
        #pragma unroll
        for (int e = 0; e < 32; e++)
            acc += qn[h * 32 + e] * Wk[t * C + h * 32 + e];
        g_qWk[t * HEADS + h] = acc;
    }
}

// ===========================================================================
// K1b: weight split (both matrices)
// ===========================================================================
__global__ void k_wcvt(const float* __restrict__ Wv, const float* __restrict__ Wo)
{
    int i = blockIdx.x * 256 + threadIdx.x;
    split2(Wv[i], g_wvhi[i], g_wvlo[i]);
    split2(Wo[i], g_wohi[i], g_wolo[i]);
}

// ===========================================================================
// K2: cost_exp + x split (fused: single pass over x)
// ===========================================================================
__global__ __launch_bounds__(256)
void k_cost(const float* __restrict__ x)
{
    __shared__ float sQ[C * HEADS];
    __shared__ float sqb[HEADS];
    int t = threadIdx.x;
    for (int i = t; i < C * HEADS; i += 256) sQ[i] = g_qWk[i];
    if (t < HEADS) sqb[t] = g_qb[t];
    __syncthreads();

    int b = blockIdx.y;
    int w = blockIdx.x * 256 + t;
    size_t bC = (size_t)b * C;
    const float* xp = x + bC * WD + w;

    float acc[HEADS];
    #pragma unroll
    for (int h = 0; h < HEADS; h++) acc[h] = sqb[h];
    for (int d = 0; d < C; d++) {
        float xv = xp[(size_t)d * WD];
        __nv_bfloat16 hh, ll;
        split2(xv, hh, ll);
        size_t off = (bC + d) * WD + w;
        g_xhi[off] = hh;
        g_xlo[off] = ll;
        #pragma unroll
        for (int h = 0; h < HEADS; h++) acc[h] += xv * sQ[d * HEADS + h];
    }
    #pragma unroll
    for (int h = 0; h < HEADS; h++)
        g_cexp[((size_t)(b * HEADS + h)) * WD + w] = expf(acc[h]);
}

// ===========================================================================
// split-bf16 mma.sync GEMM (proven 128x128 tile, warp 32x64, 2 CTAs/SM)
// K chunks of 32, 3-stage cp.async pipeline, ONE __syncthreads per chunk:
//   wait(1) -> sync -> issue chunk c+2 -> compute chunk c
// 3 passes: AhiBhi + AloBhi + AhiBlo.
// MODE 0: B = xhi/xlo, Out = g_vc, epilogue (acc+bias)*cexp
// MODE 1: B = uhi/ulo, Out = param, epilogue acc+bias
// ===========================================================================
constexpr int KC    = 32;
constexpr int OF_A  = 0;        // 128 rows x 128B (hi chunks 0-3 | lo 4-7)  16KB
constexpr int OF_BH = 16384;    // 32 rows x 256B                            8KB
constexpr int OF_BL = 24576;    //                                           8KB
constexpr int STAGE = 32768;
constexpr int GSMEM = 3 * STAGE;   // 98304

template <int MODE>
__global__ __launch_bounds__(256, 2)
void k_mma_gemm(const float* __restrict__ bias, float* __restrict__ OutP)
{
    extern __shared__ char smem[];
    uint32_t sb = smem_u32(smem);
    int t   = threadIdx.x;
    int wid = t >> 5;
    int lid = t & 31;
    int b   = blockIdx.z;
    int o0  = blockIdx.y * 128;
    int w0  = blockIdx.x * 128;
    size_t bC = (size_t)b * C;

    const __nv_bfloat16* whi = (MODE == 0) ? g_wvhi : g_wohi;
    const __nv_bfloat16* wlo = (MODE == 0) ? g_wvlo : g_wolo;
    const __nv_bfloat16* bhi = (MODE == 0) ? g_xhi : g_uhi;
    const __nv_bfloat16* blo = (MODE == 0) ? g_xlo : g_ulo;
    float* Out = (MODE == 0) ? g_vc : OutP;

    int wm = (wid >> 1) * 32;
    int wn = (wid & 1) * 64;

    float acc[2][8][4];
    #pragma unroll
    for (int f = 0; f < 2; f++)
        #pragma unroll
        for (int nf = 0; nf < 8; nf++)
            #pragma unroll
            for (int i = 0; i < 4; i++) acc[f][nf][i] = 0.f;

    auto load_chunk = [&](int k0, int stg) {
        uint32_t base = sb + stg * STAGE;
        // A: 128 rows, 8x16B chunks per row (hi 0-3 | lo 4-7), swizzled
        #pragma unroll
        for (int j = 0; j < 4; j++) {
            int l = t + 256 * j;          // 0..1023
            int row = l >> 3;
            int c = l & 7;
            const __nv_bfloat16* src = ((c < 4) ? whi : wlo)
                                       + (size_t)(o0 + row) * C + k0 + (c & 3) * 8;
            CP16(base + OF_A + row * 128 + ((c ^ (row & 7)) << 4), src);
        }
        // B: [k][n] rows of 256 B
        #pragma unroll
        for (int j = 0; j < 2; j++) {
            int l = t + 256 * j;          // 0..511
            int row = l >> 4;
            int cc = l & 15;
            size_t goff = (bC + k0 + row) * WD + w0 + cc * 8;
            uint32_t sw = row * 256 + ((cc ^ (row & 7)) << 4);
            CP16(base + OF_BH + sw, bhi + goff);
            CP16(base + OF_BL + sw, blo + goff);
        }
    };

    load_chunk(0, 0);  CP_COMMIT();
    load_chunk(KC, 1); CP_COMMIT();

    for (int c = 0; c < 8; c++) {
        if (c < 7) { CP_WAIT(1); } else { CP_WAIT(0); }
        __syncthreads();
        if (c + 2 < 8) { load_chunk((c + 2) * KC, (c + 2) % 3); CP_COMMIT(); }

        uint32_t Ab = sb + (c % 3) * STAGE + OF_A;
        uint32_t BH = sb + (c % 3) * STAGE + OF_BH;
        uint32_t BL = sb + (c % 3) * STAGE + OF_BL;

        #pragma unroll
        for (int ks = 0; ks < 2; ks++) {
            // A frags (hi + lo)
            uint32_t ah[2][4], al[2][4];
            #pragma unroll
            for (int f = 0; f < 2; f++) {
                int r  = wm + f * 16 + (lid & 15);
                int kc = 2 * ks + (lid >> 4);
                ldm_x4(ah[f], Ab + r * 128 + ((kc ^ (r & 7)) << 4));
                ldm_x4(al[f], Ab + r * 128 + (((kc + 4) ^ (r & 7)) << 4));
            }
            // B hi frags (trans ldmatrix on [k][n])
            int m    = lid >> 3;
            int krow = ks * 16 + (m & 1) * 8 + (lid & 7);
            int ccb  = (wn >> 3) + (m >> 1);
            uint32_t bh[16];
            #pragma unroll
            for (int p = 0; p < 4; p++) {
                int cc = ccb + 2 * p;
                ldm_x4_t(bh + 4 * p, BH + krow * 256 + ((cc ^ (krow & 7)) << 4));
            }
            #pragma unroll
            for (int f = 0; f < 2; f++)
                #pragma unroll
                for (int nf = 0; nf < 8; nf++) {
                    mma_bf16(acc[f][nf], ah[f], bh + 2 * nf);
                    mma_bf16(acc[f][nf], al[f], bh + 2 * nf);
                }
            // B lo frags
            uint32_t bl[16];
            #pragma unroll
            for (int p = 0; p < 4; p++) {
                int cc = ccb + 2 * p;
                ldm_x4_t(bl + 4 * p, BL + krow * 256 + ((cc ^ (krow & 7)) << 4));
            }
            #pragma unroll
            for (int f = 0; f < 2; f++)
                #pragma unroll
                for (int nf = 0; nf < 8; nf++)
                    mma_bf16(acc[f][nf], ah[f], bl + 2 * nf);
        }
    }

    __syncthreads();

    // ---- epilogue: fragment-direct float2 stores ----
    #pragma unroll
    for (int f = 0; f < 2; f++) {
        int rbase = wm + f * 16;
        int h = (o0 + rbase) >> 5;
        const float* ce = g_cexp + ((size_t)(b * HEADS + h)) * WD + w0;
        #pragma unroll
        for (int half = 0; half < 2; half++) {
            int o = o0 + rbase + (lid >> 2) + half * 8;
            float bvv = bias[o];
            float* op = Out + (bC + o) * WD + w0;
            #pragma unroll
            for (int nf = 0; nf < 8; nf++) {
                int wc = wn + nf * 8 + (lid & 3) * 2;
                float vx = acc[f][nf][half * 2 + 0];
                float vy = acc[f][nf][half * 2 + 1];
                float2 r;
                if (MODE == 0) {
                    float2 cc = *(const float2*)(ce + wc);
                    r.x = (vx + bvv) * cc.x;
                    r.y = (vy + bvv) * cc.y;
                } else {
                    r.x = vx + bvv;
                    r.y = vy + bvv;
                }
                *(float2*)(op + wc) = r;
            }
        }
    }
}

// ===========================================================================
// K4a: denominator reciprocal
// ===========================================================================
constexpr int CT = 1024;

__global__ __launch_bounds__(256)
void k_sumc(const float* __restrict__ rpe)
{
    __shared__ float sce[CT + 2 * PAD];
    __shared__ float srk[KW];
    int t  = threadIdx.x;
    int h  = blockIdx.y;
    int b  = blockIdx.z;
    int w0 = blockIdx.x * CT;

    if (t < KW) srk[t] = expf(rpe[h * KW + t]);
    const float* ce = g_cexp + ((size_t)(b * HEADS + h)) * WD;
    for (int i = t; i < CT + 2 * PAD; i += 256) {
        int g = w0 - PAD + i;
        sce[i] = (g >= 0 && g < WD) ? ce[g] : 0.f;
    }
    __syncthreads();

    float rk[KW];
    #pragma unroll
    for (int k = 0; k < KW; k++) rk[k] = srk[k];

    int base = t * 4;
    float win[34];
    #pragma unroll
    for (int j = 0; j < 34; j++) win[j] = sce[base + j];

    float s0 = 0.f, s1 = 0.f, s2 = 0.f, s3 = 0.f;
    #pragma unroll
    for (int k = 0; k < KW; k++) {
        float r = rk[k];
        s0 += r * win[k];     s1 += r * win[k + 1];
        s2 += r * win[k + 2]; s3 += r * win[k + 3];
    }
    float4 o;
    o.x = 1.f / s0; o.y = 1.f / s1; o.z = 1.f / s2; o.w = 1.f / s3;
    *(float4*)&g_srec[((size_t)(b * HEADS + h)) * WD + w0 + base] = o;
}

// ===========================================================================
// K4b: numerator conv + scale -> u split directly to bf16 hi/lo
// ===========================================================================
__global__ __launch_bounds__(256)
void k_conv(const float* __restrict__ rpe)
{
    __shared__ float svc[CT + 2 * PAD];
    __shared__ float srk[KW];
    int t  = threadIdx.x;
    int c  = blockIdx.y;
    int b  = blockIdx.z;
    int w0 = blockIdx.x * CT;
    int h  = c >> 5;

    if (t < KW) srk[t] = expf(rpe[h * KW + t]);
    const float* vcrow = g_vc + ((size_t)(b * C + c)) * WD;
    for (int i = t; i < CT + 2 * PAD; i += 256) {
        int g = w0 - PAD + i;
        svc[i] = (g >= 0 && g < WD) ? vcrow[g] : 0.f;
    }
    __syncthreads();

    float rk[KW];
    #pragma unroll
    for (int k = 0; k < KW; k++) rk[k] = srk[k];

    int base = t * 4;
    float win[34];
    #pragma unroll
    for (int j = 0; j < 34; j++) win[j] = svc[base + j];

    float s0 = 0.f, s1 = 0.f, s2 = 0.f, s3 = 0.f;
    #pragma unroll
    for (int k = 0; k < KW; k++) {
        float r = rk[k];
        s0 += r * win[k];     s1 += r * win[k + 1];
        s2 += r * win[k + 2]; s3 += r * win[k + 3];
    }
    float4 rec = *(const float4*)&g_srec[((size_t)(b * HEADS + h)) * WD + w0 + base];
    float u[4] = { s0 * rec.x, s1 * rec.y, s2 * rec.z, s3 * rec.w };

    size_t off = ((size_t)(b * C + c)) * WD + w0 + base;
    __nv_bfloat16 hh[4], ll[4];
    #pragma unroll
    for (int i = 0; i < 4; i++) split2(u[i], hh[i], ll[i]);
    *(uint2*)&g_uhi[off] = *(uint2*)hh;
    *(uint2*)&g_ulo[off] = *(uint2*)ll;
}

// ===========================================================================
extern "C" void kernel_launch(void* const* d_in, const int* in_sizes, int n_in,
                              void* d_out, int out_size)
{
    (void)in_sizes; (void)n_in; (void)out_size;
    const float* x     = (const float*)d_in[0];
    const float* query = (const float*)d_in[1];
    const float* Wk    = (const float*)d_in[2];
    const float* Wkb   = (const float*)d_in[3];
    const float* rpe   = (const float*)d_in[4];
    const float* Wv    = (const float*)d_in[5];
    const float* bv    = (const float*)d_in[6];
    const float* Wo    = (const float*)d_in[7];
    const float* bo    = (const float*)d_in[8];
    float* out = (float*)d_out;

    cudaFuncSetAttribute(k_mma_gemm<0>, cudaFuncAttributeMaxDynamicSharedMemorySize, GSMEM);
    cudaFuncSetAttribute(k_mma_gemm<1>, cudaFuncAttributeMaxDynamicSharedMemorySize, GSMEM);

    k_prep<<<1, 256>>>(query, Wk, Wkb);
    k_wcvt<<<C * C / 256, 256>>>(Wv, Wo);
    k_cost<<<dim3(WD / 256, Bsz), 256>>>(x);
    k_sumc<<<dim3(WD / CT, HEADS, Bsz), 256>>>(rpe);
    k_mma_gemm<0><<<dim3(WD / 128, C / 128, Bsz), 256, GSMEM>>>(bv, nullptr);
    k_conv<<<dim3(WD / CT, C, Bsz), 256>>>(rpe);
    k_mma_gemm<1><<<dim3(WD / 128, C / 128, Bsz), 256, GSMEM>>>(bo, out);
}